// round 4
// baseline (speedup 1.0000x reference)
#include <cuda_runtime.h>

#ifndef M_PI_F
#define M_PI_F 3.14159265358979323846f
#endif

#define FDIM   512
#define NOUT   100
#define RPB    128     // rows per block == threads per block
#define NCHK   16      // 512 / 32
#define XPAD   36      // smem row stride in floats (conflict-free for LDS.128)

// Thread-per-row GEMV through smem transpose:
//  - zero shuffles / zero cross-lane reductions
//  - coalesced float4 LDG (8 per thread in flight), smem-staged transpose
//  - circuit computed 32 rows per warp-instruction (per-thread, independent)
//  - epilogue: z staged in smem, output written as a linear coalesced float4 stream
__global__ __launch_bounds__(RPB, 7)
void qnet_fused_kernel(const float* __restrict__ X,
                       const float* __restrict__ preW,
                       const float* __restrict__ preB,
                       const float* __restrict__ qp,
                       const float* __restrict__ postW,
                       const float* __restrict__ postB,
                       float* __restrict__ out,
                       int B)
{
    __shared__ float  xsm[RPB * XPAD];       // 18 KB
    __shared__ float  wsm[3 * FDIM];         // 6 KB
    __shared__ float4 zsm[RPB];              // 2 KB
    __shared__ float  pwsm[25 * 20];         // 2 KB (post weights, padded)

    const int tid  = threadIdx.x;
    const int base = blockIdx.x * RPB;
    const int rows = min(RPB, B - base);

    // ---- stage pre_W into smem (once per block) ----
    for (int i = tid; i < 3 * FDIM; i += RPB) wsm[i] = preW[i];

    // ---- stage post weights: pwsm[g][j*4 + k] ; n = 4g+j ; k<3: W, k=3: b ----
    for (int i = tid; i < 400; i += RPB) {
        const int g = i >> 4, rem = i & 15, j = rem >> 2, k = rem & 3;
        const int n = g * 4 + j;
        pwsm[g * 20 + rem] = (k < 3) ? __ldg(postW + n * 3 + k) : __ldg(postB + n);
    }

    const float4* __restrict__ Xg = reinterpret_cast<const float4*>(X) + (size_t)base * (FDIM / 4);
    const bool full = (rows == RPB);

    // ---- prefetch chunk 0 ----
    float4 r[8];
    #pragma unroll
    for (int i = 0; i < 8; ++i) {
        const int f = i * RPB + tid;
        const int rw = f >> 3, c4 = f & 7;
        r[i] = (full || rw < rows) ? Xg[(size_t)rw * (FDIM / 4) + c4]
                                   : make_float4(0.f, 0.f, 0.f, 0.f);
    }

    float d0 = 0.f, d1 = 0.f, d2 = 0.f;

    for (int c = 0; c < NCHK; ++c) {
        __syncthreads();    // previous chunk's compute done before overwrite
        #pragma unroll
        for (int i = 0; i < 8; ++i) {
            const int f = i * RPB + tid;
            *reinterpret_cast<float4*>(&xsm[(f >> 3) * XPAD + (f & 7) * 4]) = r[i];
        }
        __syncthreads();

        // prefetch next chunk while computing this one (hides DRAM latency)
        if (c + 1 < NCHK) {
            #pragma unroll
            for (int i = 0; i < 8; ++i) {
                const int f = i * RPB + tid;
                const int rw = f >> 3, c4 = f & 7;
                r[i] = (full || rw < rows) ? Xg[(size_t)rw * (FDIM / 4) + (c + 1) * 8 + c4]
                                           : make_float4(0.f, 0.f, 0.f, 0.f);
            }
        }

        const float* __restrict__ wc0 = &wsm[c * 32];
        const float* __restrict__ wc1 = &wsm[FDIM + c * 32];
        const float* __restrict__ wc2 = &wsm[2 * FDIM + c * 32];
        const float* __restrict__ xrw = &xsm[tid * XPAD];

        #pragma unroll
        for (int j = 0; j < 8; ++j) {
            const float4 xv  = *reinterpret_cast<const float4*>(xrw + 4 * j);
            const float4 w0v = *reinterpret_cast<const float4*>(wc0 + 4 * j);  // broadcast
            const float4 w1v = *reinterpret_cast<const float4*>(wc1 + 4 * j);
            const float4 w2v = *reinterpret_cast<const float4*>(wc2 + 4 * j);
            d0 += xv.x * w0v.x + xv.y * w0v.y + xv.z * w0v.z + xv.w * w0v.w;
            d1 += xv.x * w1v.x + xv.y * w1v.y + xv.z * w1v.z + xv.w * w1v.w;
            d2 += xv.x * w2v.x + xv.y * w2v.y + xv.z * w2v.z + xv.w * w2v.w;
        }
    }

    // ---- per-thread circuit (32 independent rows per warp) ----
    const float t0 = tanhf(d0 + __ldg(preB + 0)) * (M_PI_F * 0.5f);
    const float t1 = tanhf(d1 + __ldg(preB + 1)) * (M_PI_F * 0.5f);
    const float t2 = tanhf(d2 + __ldg(preB + 2)) * (M_PI_F * 0.5f);

    float s[8];
    const float inv_sqrt8 = 0.3535533905932738f;
    #pragma unroll
    for (int i = 0; i < 8; ++i) s[i] = inv_sqrt8;

    auto ry0 = [&](float th) {
        float sn, cs; __sincosf(th * 0.5f, &sn, &cs);
        #pragma unroll
        for (int i = 0; i < 4; ++i) {
            float a = s[i], b = s[i + 4];
            s[i]     = cs * a - sn * b;
            s[i + 4] = sn * a + cs * b;
        }
    };
    auto ry1 = [&](float th) {
        float sn, cs; __sincosf(th * 0.5f, &sn, &cs);
        #pragma unroll
        for (int g = 0; g < 2; ++g)
            #pragma unroll
            for (int i = 0; i < 2; ++i) {
                int lo = g * 4 + i;
                float a = s[lo], b = s[lo + 2];
                s[lo]     = cs * a - sn * b;
                s[lo + 2] = sn * a + cs * b;
            }
    };
    auto ry2 = [&](float th) {
        float sn, cs; __sincosf(th * 0.5f, &sn, &cs);
        #pragma unroll
        for (int g = 0; g < 4; ++g) {
            int lo = g * 2;
            float a = s[lo], b = s[lo + 1];
            s[lo]     = cs * a - sn * b;
            s[lo + 1] = sn * a + cs * b;
        }
    };

    ry0(t0); ry1(t1); ry2(t2);

    #pragma unroll
    for (int k = 0; k < 2; ++k) {
        float tmp;
        tmp = s[4]; s[4] = s[6]; s[6] = tmp;   // CNOT(0,1)
        tmp = s[5]; s[5] = s[7]; s[7] = tmp;
        tmp = s[2]; s[2] = s[3]; s[3] = tmp;   // CNOT(1,2)
        tmp = s[6]; s[6] = s[7]; s[7] = tmp;
        ry0(__ldg(qp + 3 * (k + 1) + 0));
        ry1(__ldg(qp + 3 * (k + 1) + 1));
        ry2(__ldg(qp + 3 * (k + 1) + 2));
    }

    float p[8];
    #pragma unroll
    for (int i = 0; i < 8; ++i) p[i] = s[i] * s[i];

    const float z0 = (p[0] + p[1] + p[2] + p[3]) - (p[4] + p[5] + p[6] + p[7]);
    const float z1 = (p[0] + p[1] + p[4] + p[5]) - (p[2] + p[3] + p[6] + p[7]);
    const float z2 = (p[0] + p[2] + p[4] + p[6]) - (p[1] + p[3] + p[5] + p[7]);

    __syncthreads();               // xsm no longer needed; publish z
    zsm[tid] = make_float4(z0, z1, z2, 0.f);
    __syncthreads();

    // ---- epilogue: fully linear coalesced float4 output stream ----
    // out element offset = (base+row)*100 + 4g ; with f4 = row*25+g this is
    // base*100 + f4*4 -> perfectly contiguous.
    float4* __restrict__ outb = reinterpret_cast<float4*>(out + (size_t)base * NOUT);
    const int lim = rows * 25;
    #pragma unroll
    for (int i = 0; i < 25; ++i) {
        const int f4  = i * RPB + tid;
        if (!full && f4 >= lim) break;
        const int row = f4 / 25;
        const int g   = f4 - row * 25;
        const float4 z = zsm[row];
        const float4* __restrict__ pw = reinterpret_cast<const float4*>(&pwsm[g * 20]);
        const float4 p0 = pw[0], p1 = pw[1], p2 = pw[2], p3 = pw[3];
        float4 o;
        o.x = z.x * p0.x + z.y * p0.y + z.z * p0.z + p0.w;
        o.y = z.x * p1.x + z.y * p1.y + z.z * p1.z + p1.w;
        o.z = z.x * p2.x + z.y * p2.y + z.z * p2.z + p2.w;
        o.w = z.x * p3.x + z.y * p3.y + z.z * p3.z + p3.w;
        outb[f4] = o;
    }
}

extern "C" void kernel_launch(void* const* d_in, const int* in_sizes, int n_in,
                              void* d_out, int out_size)
{
    const float* X     = (const float*)d_in[0]; // [B, 512]
    const float* preW  = (const float*)d_in[1]; // [3, 512]
    const float* preB  = (const float*)d_in[2]; // [3]
    const float* qp    = (const float*)d_in[3]; // [45]
    const float* postW = (const float*)d_in[4]; // [100, 3]
    const float* postB = (const float*)d_in[5]; // [100]
    float* out = (float*)d_out;                 // [B, 100]

    const int B = in_sizes[0] / FDIM;
    const int blocks = (B + RPB - 1) / RPB;

    qnet_fused_kernel<<<blocks, RPB>>>(X, preW, preB, qp, postW, postB, out, B);
}

// round 6
// speedup vs baseline: 1.5222x; 1.5222x over previous
#include <cuda_runtime.h>

#ifndef M_PI_F
#define M_PI_F 3.14159265358979323846f
#endif

#define FDIM 512
#define NOUT 100

__device__ __forceinline__ void cp_async16(unsigned int saddr, const void* gaddr) {
    asm volatile("cp.async.cg.shared.global [%0], [%1], 16;" :: "r"(saddr), "l"(gaddr));
}
__device__ __forceinline__ void cp_commit() {
    asm volatile("cp.async.commit_group;" ::: "memory");
}
template <int N>
__device__ __forceinline__ void cp_wait() {
    asm volatile("cp.async.wait_group %0;" :: "n"(N) : "memory");
}

// Warp = 8 rows, zero block-wide syncs.
//  - X streamed via per-warp 3-stage cp.async smem ring (2 rows in flight/warp,
//    4KB/warp -> 64KB/SM in flight at 16 warps: DRAM saturating, register-free)
//  - pre_W cached in registers (48/lane), lane-sliced dot + butterfly reduce
//  - circuit per-lane (lanes 0-7 hold the 8 rows)
//  - epilogue: contiguous float4 postW loads, linear coalesced __stcs float4 writes
__global__ __launch_bounds__(256, 2)
void qnet_fused_kernel(const float* __restrict__ X,
                       const float* __restrict__ preW,
                       const float* __restrict__ preB,
                       const float* __restrict__ qp,
                       const float* __restrict__ postW,
                       const float* __restrict__ postB,
                       float* __restrict__ out,
                       int B)
{
    __shared__ float4 xring[8][3][128];   // 8 warps x 3 stages x 2KB = 48KB

    const int tid  = threadIdx.x;
    const int wid  = tid >> 5;
    const int lane = tid & 31;
    const int wbase = (blockIdx.x * 8 + wid) * 8;
    if (wbase >= B) return;
    const int rows = min(8, B - wbase);

    // ---- pre_W in registers: lane covers float4 cols {lane, lane+32, +64, +96} ----
    const float4* __restrict__ W4 = reinterpret_cast<const float4*>(preW);
    float4 wa[4], wb[4], wc[4];
    #pragma unroll
    for (int k = 0; k < 4; ++k) {
        const int i = lane + 32 * k;
        wa[k] = __ldg(W4 + i);
        wb[k] = __ldg(W4 + 128 + i);
        wc[k] = __ldg(W4 + 256 + i);
    }

    const float4* __restrict__ X4 = reinterpret_cast<const float4*>(X);

    // ---- cp.async stage issue: row -> stage (row % 3) of this warp's ring ----
    auto issue = [&](int r) {
        const int grow = wbase + min(r, rows - 1);       // clamp tail
        const float4* __restrict__ src = X4 + (size_t)grow * 128;
        const int st = r % 3;
        #pragma unroll
        for (int k = 0; k < 4; ++k) {
            unsigned int sa = (unsigned int)__cvta_generic_to_shared(&xring[wid][st][lane + 32 * k]);
            cp_async16(sa, src + lane + 32 * k);
        }
        cp_commit();
    };

    issue(0);
    issue(1);

    const int myrow = lane & 7;
    float a0 = 0.f, a1 = 0.f, a2 = 0.f;

    #pragma unroll
    for (int r = 0; r < 8; ++r) {
        if (r < 6) issue(r + 2);                 // fill stage (r-1)%3 (consumed)
        if (r < 6)      cp_wait<2>();
        else if (r == 6) cp_wait<1>();
        else             cp_wait<0>();
        __syncwarp();

        const int st = r % 3;
        float d0 = 0.f, d1 = 0.f, d2 = 0.f;
        #pragma unroll
        for (int k = 0; k < 4; ++k) {
            const float4 xv = xring[wid][st][lane + 32 * k];
            d0 += xv.x * wa[k].x + xv.y * wa[k].y + xv.z * wa[k].z + xv.w * wa[k].w;
            d1 += xv.x * wb[k].x + xv.y * wb[k].y + xv.z * wb[k].z + xv.w * wb[k].w;
            d2 += xv.x * wc[k].x + xv.y * wc[k].y + xv.z * wc[k].z + xv.w * wc[k].w;
        }
        #pragma unroll
        for (int off = 16; off > 0; off >>= 1) {
            d0 += __shfl_xor_sync(0xFFFFFFFFu, d0, off);
            d1 += __shfl_xor_sync(0xFFFFFFFFu, d1, off);
            d2 += __shfl_xor_sync(0xFFFFFFFFu, d2, off);
        }
        if (myrow == r) { a0 = d0; a1 = d1; a2 = d2; }
    }

    // ---- per-lane circuit: lane l (l<8) simulates row l ----
    const float t0 = tanhf(a0 + __ldg(preB + 0)) * (M_PI_F * 0.5f);
    const float t1 = tanhf(a1 + __ldg(preB + 1)) * (M_PI_F * 0.5f);
    const float t2 = tanhf(a2 + __ldg(preB + 2)) * (M_PI_F * 0.5f);

    float s[8];
    const float inv_sqrt8 = 0.3535533905932738f;
    #pragma unroll
    for (int i = 0; i < 8; ++i) s[i] = inv_sqrt8;

    auto ry0 = [&](float th) {
        float sn, cs; __sincosf(th * 0.5f, &sn, &cs);
        #pragma unroll
        for (int i = 0; i < 4; ++i) {
            float a = s[i], b = s[i + 4];
            s[i]     = cs * a - sn * b;
            s[i + 4] = sn * a + cs * b;
        }
    };
    auto ry1 = [&](float th) {
        float sn, cs; __sincosf(th * 0.5f, &sn, &cs);
        #pragma unroll
        for (int g = 0; g < 2; ++g)
            #pragma unroll
            for (int i = 0; i < 2; ++i) {
                int lo = g * 4 + i;
                float a = s[lo], b = s[lo + 2];
                s[lo]     = cs * a - sn * b;
                s[lo + 2] = sn * a + cs * b;
            }
    };
    auto ry2 = [&](float th) {
        float sn, cs; __sincosf(th * 0.5f, &sn, &cs);
        #pragma unroll
        for (int g = 0; g < 4; ++g) {
            int lo = g * 2;
            float a = s[lo], b = s[lo + 1];
            s[lo]     = cs * a - sn * b;
            s[lo + 1] = sn * a + cs * b;
        }
    };

    ry0(t0); ry1(t1); ry2(t2);

    #pragma unroll
    for (int k = 0; k < 2; ++k) {
        float tmp;
        tmp = s[4]; s[4] = s[6]; s[6] = tmp;   // CNOT(0,1)
        tmp = s[5]; s[5] = s[7]; s[7] = tmp;
        tmp = s[2]; s[2] = s[3]; s[3] = tmp;   // CNOT(1,2)
        tmp = s[6]; s[6] = s[7]; s[7] = tmp;
        ry0(__ldg(qp + 3 * (k + 1) + 0));
        ry1(__ldg(qp + 3 * (k + 1) + 1));
        ry2(__ldg(qp + 3 * (k + 1) + 2));
    }

    float p[8];
    #pragma unroll
    for (int i = 0; i < 8; ++i) p[i] = s[i] * s[i];

    const float z0 = (p[0] + p[1] + p[2] + p[3]) - (p[4] + p[5] + p[6] + p[7]);
    const float z1 = (p[0] + p[1] + p[4] + p[5]) - (p[2] + p[3] + p[6] + p[7]);
    const float z2 = (p[0] + p[2] + p[4] + p[6]) - (p[1] + p[3] + p[5] + p[7]);

    // ---- epilogue: warp writes 8 rows x 25 float4, perfectly contiguous ----
    const float4* __restrict__ pW4 = reinterpret_cast<const float4*>(postW);  // 75 float4
    const float4* __restrict__ pB4 = reinterpret_cast<const float4*>(postB);  // 25 float4
    float4* __restrict__ out4 = reinterpret_cast<float4*>(out) + (size_t)wbase * 25;
    const int lim = rows * 25;

    #pragma unroll
    for (int i = 0; i < 7; ++i) {
        const int f4  = i * 32 + lane;          // 0..223 ; valid < 200
        const int row = f4 / 25;
        const int g   = f4 - row * 25;
        const float zz0 = __shfl_sync(0xFFFFFFFFu, z0, row & 7);
        const float zz1 = __shfl_sync(0xFFFFFFFFu, z1, row & 7);
        const float zz2 = __shfl_sync(0xFFFFFFFFu, z2, row & 7);
        if (f4 < lim) {
            // outputs n = 4g..4g+3 ; postW floats 12g..12g+11 contiguous
            const float4 f0 = __ldg(pW4 + 3 * g + 0);
            const float4 f1 = __ldg(pW4 + 3 * g + 1);
            const float4 f2 = __ldg(pW4 + 3 * g + 2);
            const float4 bb = __ldg(pB4 + g);
            float4 o;
            o.x = zz0 * f0.x + zz1 * f0.y + zz2 * f0.z + bb.x;
            o.y = zz0 * f0.w + zz1 * f1.x + zz2 * f1.y + bb.y;
            o.z = zz0 * f1.z + zz1 * f1.w + zz2 * f2.x + bb.z;
            o.w = zz0 * f2.y + zz1 * f2.z + zz2 * f2.w + bb.w;
            __stcs(out4 + f4, o);
        }
    }
}

extern "C" void kernel_launch(void* const* d_in, const int* in_sizes, int n_in,
                              void* d_out, int out_size)
{
    const float* X     = (const float*)d_in[0]; // [B, 512]
    const float* preW  = (const float*)d_in[1]; // [3, 512]
    const float* preB  = (const float*)d_in[2]; // [3]
    const float* qp    = (const float*)d_in[3]; // [45]
    const float* postW = (const float*)d_in[4]; // [100, 3]
    const float* postB = (const float*)d_in[5]; // [100]
    float* out = (float*)d_out;                 // [B, 100]

    const int B = in_sizes[0] / FDIM;
    const int blocks = (B + 63) / 64;           // 8 warps x 8 rows per block

    qnet_fused_kernel<<<blocks, 256>>>(X, preW, preB, qp, postW, postB, out, B);
}